// round 15
// baseline (speedup 1.0000x reference)
#include <cuda_runtime.h>

#define NMAX   1000000
#define NCELLS 220000
#define GX 220
#define GY 250

// -------------------- static scratch --------------------
static __device__ int    d_key[NMAX];
static __device__ int    d_rank[NMAX];
static __device__ __align__(8) int2 d_pvinv[NMAX];     // {voxel id, original index}
static __device__ int    d_cnt[NCELLS];
static __device__ int    d_cellvid[NCELLS];
static __device__ int    d_cellstart[NCELLS];
static __device__ float  d_sums[NCELLS * 3];
static __device__ float  d_mean[NCELLS * 3];
static __device__ int    d_voxstart[NCELLS + 1];
static __device__ int    d_voxcnt[NCELLS];
static __device__ int    d_voxcell[NCELLS];
static __device__ __align__(16) float d_x[(size_t)NMAX * 32];
static __device__ __align__(16) float d_xmax[(size_t)NCELLS * 32];
static __device__ __align__(16) float d_xsum[(size_t)NCELLS * 32];
static __device__ __align__(16) float d_w1p[4096];   // sc-scaled top weights (32x128)
static __device__ __align__(16) float d_w1b[4096];   // sc-scaled bottom weights (32x128)
static __device__ double d_S0t[55];   // 10x10 Gram, upper triangle
static __device__ double d_svf[10];
static __device__ double d_SA[1024];
static __device__ double d_SB[1024];
static __device__ double d_SC[1024];
static __device__ double d_svx[32];
static __device__ double d_svm[32];
static __device__ float  d_bn0[64];
static __device__ float  d_bn1[256];
static __device__ unsigned long long d_bsum[256];
static __device__ int    d_meta[2];    // [0]=V, [1]=Nvalid

__device__ __forceinline__ int3 coordsOf(float x, float y, float z) {
    int ix = (int)floorf(__fdiv_rn(x, 0.32f));
    int iy = (int)floorf(__fdiv_rn(__fadd_rn(y, 40.0f), 0.32f));
    int iz = (int)floorf(__fdiv_rn(__fadd_rn(z, 3.0f), 4.0f));
    return make_int3(ix, iy, iz);
}
__device__ __forceinline__ unsigned long long splat2(float v) {
    unsigned long long r;
    asm("mov.b64 %0, {%1, %1};" : "=l"(r) : "r"(__float_as_uint(v)));
    return r;
}
__device__ __forceinline__ unsigned long long pack2(float a, float b) {
    unsigned long long r;
    asm("mov.b64 %0, {%1, %2};" : "=l"(r) : "r"(__float_as_uint(a)), "r"(__float_as_uint(b)));
    return r;
}
__device__ __forceinline__ void unpack2(unsigned long long p, float& a, float& b) {
    unsigned int lo, hi;
    asm("mov.b64 {%0, %1}, %2;" : "=r"(lo), "=r"(hi) : "l"(p));
    a = __uint_as_float(lo); b = __uint_as_float(hi);
}
#define FMA2(acc, a, b) asm("fma.rn.f32x2 %0, %1, %2, %0;" : "+l"(acc) : "l"(a), "l"(b))

// -------------------- K0: zero --------------------
__global__ void k_zero() {
    int i = blockIdx.x * blockDim.x + threadIdx.x;
    if (i < NCELLS) {
        d_cnt[i] = 0;
        d_sums[i * 3 + 0] = 0.f; d_sums[i * 3 + 1] = 0.f; d_sums[i * 3 + 2] = 0.f;
    }
    if (i < 1024) { d_SA[i] = 0.0; d_SB[i] = 0.0; d_SC[i] = 0.0; }
    if (i < 55)   d_S0t[i] = 0.0;
    if (i < 10)   d_svf[i] = 0.0;
    if (i < 32)   { d_svx[i] = 0.0; d_svm[i] = 0.0; }
}

// -------------------- K1: keys + histogram (rank) + xyz sums --------------------
__global__ void k_points(const float* __restrict__ pts, int n) {
    int i = blockIdx.x * blockDim.x + threadIdx.x;
    if (i >= n) return;
    const float* p = pts + (size_t)i * 5;
    float b = p[0], x = p[1], y = p[2], z = p[3];
    int3 c = coordsOf(x, y, z);
    int key = -1;
    if (c.x >= 0 && c.x < GX && c.y >= 0 && c.y < GY && c.z == 0) {
        key = (int)b * 55000 + c.x * 250 + c.y;
        if (key < 0 || key >= NCELLS) key = -1;
    }
    d_key[i] = key;
    if (key >= 0) {
        d_rank[i] = atomicAdd(&d_cnt[key], 1);
        atomicAdd(&d_sums[key * 3 + 0], x);
        atomicAdd(&d_sums[key * 3 + 1], y);
        atomicAdd(&d_sums[key * 3 + 2], z);
    }
}

// -------------------- K2: packed scans (shfl) --------------------
__global__ void k_scan1() {
    __shared__ unsigned long long wsum[32];
    int tid = threadIdx.x;
    int wid = tid >> 5, lane = tid & 31;
    int c = blockIdx.x * 1024 + tid;
    unsigned long long v = 0ULL;
    if (c < NCELLS) {
        int cn = d_cnt[c];
        v = ((unsigned long long)(cn > 0) << 32) | (unsigned int)cn;
    }
    unsigned long long s = v;
#pragma unroll
    for (int o = 1; o < 32; o <<= 1) {
        unsigned long long t = __shfl_up_sync(0xffffffffu, s, o);
        if (lane >= o) s += t;
    }
    if (lane == 31) wsum[wid] = s;
    __syncthreads();
    if (wid == 0) {
        unsigned long long ws = wsum[lane];
        unsigned long long t2 = ws;
#pragma unroll
        for (int o = 1; o < 32; o <<= 1) {
            unsigned long long t = __shfl_up_sync(0xffffffffu, t2, o);
            if (lane >= o) t2 += t;
        }
        wsum[lane] = t2 - ws;   // exclusive warp offsets
    }
    __syncthreads();
    unsigned long long exc = s - v + wsum[wid];
    if (c < NCELLS) {
        d_cellvid[c]   = (int)(exc >> 32);
        d_cellstart[c] = (int)(exc & 0xffffffffULL);
    }
    if (tid == 1023) d_bsum[blockIdx.x] = exc + v;
}

__global__ void k_scan2(int nb) {
    __shared__ unsigned long long s[256];
    int t = threadIdx.x;
    unsigned long long v = (t < nb) ? d_bsum[t] : 0ULL;
    s[t] = v;
    __syncthreads();
    for (int o = 1; o < 256; o <<= 1) {
        unsigned long long u = (t >= o) ? s[t - o] : 0ULL;
        __syncthreads();
        s[t] += u;
        __syncthreads();
    }
    if (t < nb) d_bsum[t] = s[t] - v;
    if (t == 255) {
        d_meta[0] = (int)(s[255] >> 32);
        d_meta[1] = (int)(s[255] & 0xffffffffULL);
    }
}

// -------------------- K3: finalize cells + coords output --------------------
__global__ void k_cells(float* __restrict__ out, int Vh) {
    int c = blockIdx.x * blockDim.x + threadIdx.x;
    if (c >= NCELLS) return;
    unsigned long long off = d_bsum[c >> 10];
    int vid = d_cellvid[c]   + (int)(off >> 32);
    int cst = d_cellstart[c] + (int)(off & 0xffffffffULL);
    d_cellvid[c] = vid;
    d_cellstart[c] = cst;
    int cn = d_cnt[c];
    if (cn > 0) {
        d_voxstart[vid] = cst;
        d_voxcnt[vid]   = cn;
        d_voxcell[vid]  = c;
        float fn = (float)cn;
        d_mean[vid * 3 + 0] = d_sums[c * 3 + 0] / fn;
        d_mean[vid * 3 + 1] = d_sums[c * 3 + 1] / fn;
        d_mean[vid * 3 + 2] = d_sums[c * 3 + 2] / fn;
        if (vid < Vh) {
            int b = c / 55000; int rem = c - b * 55000;
            int cx = rem / 250; int cy = rem - cx * 250;
            float* oc = out + (size_t)Vh * 128 + (size_t)vid * 4;
            oc[0] = (float)b; oc[1] = 0.f; oc[2] = (float)cy; oc[3] = (float)cx;
        }
    }
}

// -------------------- K4: scatter (vid,idx) + 10x10 Gram (fused) ----------------
__global__ void __launch_bounds__(256) k_scatfeat(const float* __restrict__ pts, int n) {
    float G[55], sv[10];
#pragma unroll
    for (int j = 0; j < 55; j++) G[j] = 0.f;
#pragma unroll
    for (int j = 0; j < 10; j++) sv[j] = 0.f;

    const float XO = (float)(0.32 / 2 + 0.0);
    const float YO = (float)(0.32 / 2 - 40.0);
    const float ZO = (float)(4.0 / 2 - 3.0);

    for (int i = blockIdx.x * blockDim.x + threadIdx.x; i < n;
         i += gridDim.x * blockDim.x) {
        int k = d_key[i];
        if (k < 0) continue;
        const float* p = pts + (size_t)i * 5;
        float x = p[1], y = p[2], z = p[3], it = p[4];
        int3 c = coordsOf(x, y, z);
        int v = d_cellvid[k];
        int pos = d_cellstart[k] + d_rank[i];
        d_pvinv[pos] = make_int2(v, i);
        float f[10];
        f[0] = x; f[1] = y; f[2] = z; f[3] = it;
        f[4] = x - d_mean[v * 3 + 0];
        f[5] = y - d_mean[v * 3 + 1];
        f[6] = z - d_mean[v * 3 + 2];
        f[7] = x - ((float)c.x * 0.32f + XO);
        f[8] = y - ((float)c.y * 0.32f + YO);
        f[9] = z - ZO;
        int gi = 0;
#pragma unroll
        for (int a = 0; a < 10; a++) {
            sv[a] += f[a];
#pragma unroll
            for (int bb = a; bb < 10; bb++) {
                G[gi] = fmaf(f[a], f[bb], G[gi]);
                gi++;
            }
        }
    }

    __shared__ float red[8][66];
    int w = threadIdx.x >> 5, lane = threadIdx.x & 31;
#pragma unroll
    for (int j = 0; j < 55; j++) {
        float v = G[j];
#pragma unroll
        for (int o = 16; o > 0; o >>= 1) v += __shfl_xor_sync(0xffffffffu, v, o);
        if (lane == 0) red[w][j] = v;
    }
#pragma unroll
    for (int j = 0; j < 10; j++) {
        float v = sv[j];
#pragma unroll
        for (int o = 16; o > 0; o >>= 1) v += __shfl_xor_sync(0xffffffffu, v, o);
        if (lane == 0) red[w][55 + j] = v;
    }
    __syncthreads();
    int t = threadIdx.x;
    if (t < 65) {
        float a = 0.f;
#pragma unroll
        for (int j = 0; j < 8; j++) a += red[j][t];
        if (t < 55) atomicAdd(&d_S0t[t], (double)a);
        else        atomicAdd(&d_svf[t - 55], (double)a);
    }
}

// -------------------- K5: BN0 params (triangular Gram) --------------------
__device__ __forceinline__ float S0at(int i, int j) {
    if (i > j) { int t = i; i = j; j = t; }
    int idx = i * 10 - (i * (i - 1)) / 2 + (j - i);
    return (float)d_S0t[idx];
}

__global__ void k_bnfin0(const float* __restrict__ g, const float* __restrict__ b,
                         const float* __restrict__ w0) {
    int c = threadIdx.x;
    if (c >= 32) return;
    float n = (float)d_meta[1];
    float sm = 0.f;
#pragma unroll
    for (int k = 0; k < 10; k++) sm = fmaf((float)d_svf[k], w0[k * 32 + c], sm);
    float mu = sm / n;
    float sq = 0.f;
    for (int i = 0; i < 10; i++) {
        float wi = w0[i * 32 + c];
        float row = 0.f;
        for (int j = 0; j < 10; j++)
            row = fmaf(S0at(i, j), w0[j * 32 + c], row);
        sq = fmaf(wi, row, sq);
    }
    float var = sq / n - mu * mu;
    float istd = rsqrtf(var + 1e-3f);
    float sc = g[c] * istd;
    d_bn0[c] = sc;
    d_bn0[32 + c] = b[c] - mu * sc;
}

// -------------------- K6: layer0 via per-voxel affine form + xmax + xsum --------
__global__ void __launch_bounds__(256) k_l0post(const float* __restrict__ pts,
                                                const float* __restrict__ w0) {
    int t = threadIdx.x;
    int w = t >> 5, lane = t & 31;
    float wc[10];
#pragma unroll
    for (int k = 0; k < 10; k++) wc[k] = w0[k * 32 + lane];
    float sc = d_bn0[lane], sh = d_bn0[32 + lane];
    float WX = (wc[0] + wc[4] + wc[7]) * sc;
    float WY = (wc[1] + wc[5] + wc[8]) * sc;
    float WZ = (wc[2] + wc[6] + wc[9]) * sc;
    float WI = wc[3] * sc;
    const float XO = (float)(0.32 / 2 + 0.0);
    const float YO = (float)(0.32 / 2 - 40.0);
    const float ZO = (float)(4.0 / 2 - 3.0);
    int V = d_meta[0];
    for (int v = blockIdx.x * 8 + w; v < V; v += gridDim.x * 8) {
        int st = d_voxstart[v], en = st + d_voxcnt[v];
        int c = d_voxcell[v];
        float mx = d_mean[v * 3 + 0], my = d_mean[v * 3 + 1], mz = d_mean[v * 3 + 2];
        int rem = c % 55000;
        float CCX = (float)(rem / 250) * 0.32f + XO;
        float CCY = (float)(rem % 250) * 0.32f + YO;
        float K = sh - (mx * wc[4] + my * wc[5] + mz * wc[6] +
                        CCX * wc[7] + CCY * wc[8] + ZO * wc[9]) * sc;
        float m = 0.f, s = 0.f;
        for (int p = st; p < en; p++) {
            int ii = d_pvinv[p].y;
            const float* pp = pts + (size_t)ii * 5;
            float pv = (lane < 4) ? pp[1 + lane] : 0.f;
            float px = __shfl_sync(0xffffffffu, pv, 0);
            float py = __shfl_sync(0xffffffffu, pv, 1);
            float pz = __shfl_sync(0xffffffffu, pv, 2);
            float pi = __shfl_sync(0xffffffffu, pv, 3);
            float y = fmaf(px, WX, fmaf(py, WY, fmaf(pz, WZ, fmaf(pi, WI, K))));
            float x = fmaxf(y, 0.f);
            d_x[(size_t)p * 32 + lane] = x;
            m = fmaxf(m, x); s += x;
        }
        d_xmax[(size_t)v * 32 + lane] = m;
        d_xsum[(size_t)v * 32 + lane] = s;
    }
}

// -------------------- K7: SA = Σ x xᵀ (4x4 tiles, low crossbar) -----------------
__global__ void __launch_bounds__(256) k_statsA() {
    __shared__ __align__(16) float xs[1024];
    __shared__ float red[4][64][16];
    int t = threadIdx.x;
    int g = t >> 6, u = t & 63;
    int r4 = ((u >> 3) & 7) << 2, c4 = (u & 7) << 2;
    int N = d_meta[1];
    int N32 = N * 32;
    int nch = (N + 31) >> 5;
    unsigned long long acc[8];
#pragma unroll
    for (int j = 0; j < 8; j++) acc[j] = 0ULL;
    for (int ch = blockIdx.x; ch < nch; ch += gridDim.x) {
        int base = ch * 1024 + t * 4;
        float4 v = make_float4(0.f, 0.f, 0.f, 0.f);
        if (base < N32) v = *(const float4*)(d_x + base);
        *(float4*)&xs[t * 4] = v;
        __syncthreads();
#pragma unroll 4
        for (int pp = 0; pp < 8; pp++) {
            int p = g * 8 + pp;
            float4 xc = *(float4*)&xs[p * 32 + c4];
            unsigned long long c01 = pack2(xc.x, xc.y);
            unsigned long long c23 = pack2(xc.z, xc.w);
#pragma unroll
            for (int j = 0; j < 4; j++) {
                unsigned long long xr2 = splat2(xs[p * 32 + r4 + j]);
                FMA2(acc[2 * j], xr2, c01);
                FMA2(acc[2 * j + 1], xr2, c23);
            }
        }
        __syncthreads();
    }
    float vals[16];
#pragma unroll
    for (int j = 0; j < 8; j++) unpack2(acc[j], vals[2 * j], vals[2 * j + 1]);
#pragma unroll
    for (int k = 0; k < 16; k++) red[g][u][k] = vals[k];
    __syncthreads();
    if (t < 64) {
#pragma unroll
        for (int k = 0; k < 16; k++) {
            float s = red[0][t][k] + red[1][t][k] + red[2][t][k] + red[3][t][k];
            int jr = k >> 2, jc = k & 3;
            atomicAdd(&d_SA[(r4 + jr) * 32 + c4 + jc], (double)s);
        }
    }
}

// -------------------- K8: SB, SC, svx, svm --------------------
__global__ void __launch_bounds__(256) k_statsBC() {
    __shared__ __align__(16) float ms[1024];
    __shared__ __align__(16) float sxs[1024];
    __shared__ float cnf[32];
    int t = threadIdx.x;
    int V = d_meta[0];
    int V32 = V * 32;
    int nch = (V + 31) >> 5;
    int r = t >> 3, c4 = (t & 7) << 2;
    unsigned long long B01 = 0, B23 = 0, C01 = 0, C23 = 0;
    float vx[4] = {0, 0, 0, 0}, vm[4] = {0, 0, 0, 0};
    for (int ch = blockIdx.x; ch < nch; ch += gridDim.x) {
        int base = ch * 1024 + t * 4;
        float4 mv = make_float4(0, 0, 0, 0), sv = make_float4(0, 0, 0, 0);
        if (base < V32) {
            mv = *(const float4*)(d_xmax + base);
            sv = *(const float4*)(d_xsum + base);
        }
        *(float4*)&ms[t * 4] = mv;
        *(float4*)&sxs[t * 4] = sv;
        if (t < 32) {
            int vv = ch * 32 + t;
            cnf[t] = (vv < V) ? (float)d_voxcnt[vv] : 0.f;
        }
        __syncthreads();
#pragma unroll 4
        for (int p = 0; p < 32; p++) {
            float cn = cnf[p];
            unsigned long long sxr2 = splat2(sxs[p * 32 + r]);
            unsigned long long cmr2 = splat2(cn * ms[p * 32 + r]);
            float4 m4 = *(float4*)&ms[p * 32 + c4];
            unsigned long long m01 = pack2(m4.x, m4.y);
            unsigned long long m23 = pack2(m4.z, m4.w);
            FMA2(B01, sxr2, m01); FMA2(B23, sxr2, m23);
            FMA2(C01, cmr2, m01); FMA2(C23, cmr2, m23);
            if (t < 8) {
                float4 sx4 = *(float4*)&sxs[p * 32 + c4];
                vx[0] += sx4.x; vx[1] += sx4.y; vx[2] += sx4.z; vx[3] += sx4.w;
                vm[0] = fmaf(cn, m4.x, vm[0]); vm[1] = fmaf(cn, m4.y, vm[1]);
                vm[2] = fmaf(cn, m4.z, vm[2]); vm[3] = fmaf(cn, m4.w, vm[3]);
            }
        }
        __syncthreads();
    }
    float b0, b1, b2, b3, c0, c1, c2, c3;
    unpack2(B01, b0, b1); unpack2(B23, b2, b3);
    unpack2(C01, c0, c1); unpack2(C23, c2, c3);
    atomicAdd(&d_SB[r * 32 + c4 + 0], (double)b0);
    atomicAdd(&d_SB[r * 32 + c4 + 1], (double)b1);
    atomicAdd(&d_SB[r * 32 + c4 + 2], (double)b2);
    atomicAdd(&d_SB[r * 32 + c4 + 3], (double)b3);
    atomicAdd(&d_SC[r * 32 + c4 + 0], (double)c0);
    atomicAdd(&d_SC[r * 32 + c4 + 1], (double)c1);
    atomicAdd(&d_SC[r * 32 + c4 + 2], (double)c2);
    atomicAdd(&d_SC[r * 32 + c4 + 3], (double)c3);
    if (t < 8) {
#pragma unroll
        for (int j = 0; j < 4; j++) {
            atomicAdd(&d_svx[c4 + j], (double)vx[j]);
            atomicAdd(&d_svm[c4 + j], (double)vm[j]);
        }
    }
}

// -------------------- K9: BN1 params --------------------
__device__ __forceinline__ float S64(int i, int j) {
    if (i < 32) {
        if (j < 32) return (float)d_SA[i * 32 + j];
        return (float)d_SB[i * 32 + (j - 32)];
    } else {
        if (j < 32) return (float)d_SB[j * 32 + (i - 32)];
        return (float)d_SC[(i - 32) * 32 + (j - 32)];
    }
}

__global__ void k_bnfin1(const float* __restrict__ w1, const float* __restrict__ g,
                         const float* __restrict__ b) {
    __shared__ float wc[64];
    __shared__ float red[64];
    __shared__ float red2[64];
    int c = blockIdx.x;
    int i = threadIdx.x;
    float wi = w1[i * 128 + c];
    wc[i] = wi;
    float sv = (i < 32) ? (float)d_svx[i] : (float)d_svm[i - 32];
    __syncthreads();
    float row = 0.f;
    for (int j = 0; j < 64; j++) row = fmaf(S64(i, j), wc[j], row);
    red[i] = wi * row;
    red2[i] = sv * wi;
    __syncthreads();
    for (int o = 32; o > 0; o >>= 1) {
        if (i < o) { red[i] += red[i + o]; red2[i] += red2[i + o]; }
        __syncthreads();
    }
    if (i == 0) {
        float n = (float)d_meta[1];
        float mu = red2[0] / n;
        float var = red[0] / n - mu * mu;
        float istd = rsqrtf(var + 1e-3f);
        float sc = g[c] * istd;
        d_bn1[c] = sc;
        d_bn1[128 + c] = b[c] - mu * sc;
    }
}

// -------------------- K10: pre-scale weights + voxstart sentinel ----------------
__global__ void k_prepw(const float* __restrict__ w1) {
    int i = blockIdx.x * blockDim.x + threadIdx.x;
    if (i == 0) d_voxstart[d_meta[0]] = d_meta[1];
    if (i < 4096) {
        float sc = d_bn1[i & 127];
        d_w1p[i] = w1[i] * sc;
        d_w1b[i] = w1[4096 + i] * sc;
    }
}

// -------------------- K11: fused point GEMM + seg max + voxel GEMM + out --------
// smem ~97KB -> 2 CTAs/SM (16 warps) for latency hiding.
__global__ void __launch_bounds__(256, 2) k_l1a(float* __restrict__ out, int Vh) {
    __shared__ __align__(16) float wst[4096];                 // Wtop'
    __shared__ __align__(16) float wsb[4096];                 // Wbot'
    __shared__ __align__(16) unsigned long long xsp[8][256];
    __shared__ __align__(16) float stash[8][12][128];         // 48KB ring (12 slots)
    __shared__ int svid[8][12];
    __shared__ int vids[8][9];
    for (int j = threadIdx.x; j < 1024; j += 256) {
        ((float4*)wst)[j] = ((const float4*)d_w1p)[j];
        ((float4*)wsb)[j] = ((const float4*)d_w1b)[j];
    }
    __syncthreads();
    int w = threadIdx.x >> 5, lane = threadIdx.x & 31;
    int N = d_meta[1], V = d_meta[0];
    int nw = gridDim.x * 8;
    int gw = blockIdx.x * 8 + w;
    int CH = (N + nw - 1) / nw;
    int lo = gw * CH;
    if (lo >= N) return;
    int hi = min(N, lo + CH);
    int a = 0, b = V;
    while (a < b) { int m = (a + b) >> 1; if (d_voxstart[m] < lo) a = m + 1; else b = m; }
    int vb = a;
    int a2 = vb, b2 = V;
    while (a2 < b2) { int m = (a2 + b2) >> 1; if (d_voxstart[m] < hi) a2 = m + 1; else b2 = m; }
    int pst = d_voxstart[vb];
    int pen = d_voxstart[a2];
    if (pst >= pen) return;

    const float NEG = __int_as_float(0xff800000);
    const float* wlT = wst + lane * 4;
    const float* wlB = wsb + lane * 4;
    float4 sh4 = *(const float4*)(d_bn1 + 128 + lane * 4);
    float m0 = NEG, m1 = NEG, m2 = NEG, m3 = NEG;
    int cur = -1, ns = 0, head = 0;

    // drain up to 4 oldest stashed voxels (uses xsp as staging; only called
    // after the point-GEMM of the current group has consumed xsp).
    auto drain = [&](int count) {
        for (int j = lane; j < 32; j += 32) { }   // no-op keep compiler calm
        for (int j = lane; j < 64; j += 32) {
            int p = j >> 3, q = j & 7;
            float4 v = make_float4(0.f, 0.f, 0.f, 0.f);
            if (p < count) {
                int slot = head + p; if (slot >= 12) slot -= 12;
                int gv = svid[w][slot];
                v = *(const float4*)(d_xmax + (size_t)gv * 32 + q * 4);
            }
            unsigned long long* d = &xsp[w][p * 32 + q * 4];
            d[0] = splat2(v.x); d[1] = splat2(v.y); d[2] = splat2(v.z); d[3] = splat2(v.w);
        }
        __syncwarp();
        unsigned long long b0[4], b1[4];
#pragma unroll
        for (int p = 0; p < 4; p++) { b0[p] = 0ULL; b1[p] = 0ULL; }
#pragma unroll 4
        for (int k2 = 0; k2 < 16; k2++) {
            ulonglong2 wA = *(const ulonglong2*)(wlB + (2 * k2) * 128);
            ulonglong2 wB = *(const ulonglong2*)(wlB + (2 * k2 + 1) * 128);
#pragma unroll
            for (int p = 0; p < 4; p++) {
                ulonglong2 xv = *(const ulonglong2*)&xsp[w][p * 32 + 2 * k2];
                FMA2(b0[p], xv.x, wA.x); FMA2(b1[p], xv.x, wA.y);
                FMA2(b0[p], xv.y, wB.x); FMA2(b1[p], xv.y, wB.y);
            }
        }
        __syncwarp();
#pragma unroll
        for (int p = 0; p < 4; p++) {
            if (p >= count) break;
            int slot = head + p; if (slot >= 12) slot -= 12;
            int vv = svid[w][slot];
            float y0, y1, y2, y3;
            unpack2(b0[p], y0, y1); unpack2(b1[p], y2, y3);
            float4 mm = *(float4*)&stash[w][slot][lane * 4];
            if (vv < Vh) {
                float o0 = fmaxf(mm.x + y0 + sh4.x, 0.f);
                float o1 = fmaxf(mm.y + y1 + sh4.y, 0.f);
                float o2 = fmaxf(mm.z + y2 + sh4.z, 0.f);
                float o3 = fmaxf(mm.w + y3 + sh4.w, 0.f);
                *(float4*)(out + (size_t)vv * 128 + lane * 4) = make_float4(o0, o1, o2, o3);
            }
        }
        head += count; if (head >= 12) head -= 12;
        ns -= count;
    };

    for (int base = pst; base < pen; base += 8) {
        for (int j = lane; j < 64; j += 32) {
            int p = j >> 3, q = j & 7;
            int gp = base + p;
            float4 v = make_float4(0.f, 0.f, 0.f, 0.f);
            if (gp < pen) v = *(const float4*)(d_x + (size_t)gp * 32 + q * 4);
            unsigned long long* d = &xsp[w][p * 32 + q * 4];
            d[0] = splat2(v.x); d[1] = splat2(v.y); d[2] = splat2(v.z); d[3] = splat2(v.w);
        }
        if (lane < 9) vids[w][lane] = (base + lane < pen) ? d_pvinv[base + lane].x : -1;
        __syncwarp();
        unsigned long long a0[8], a1[8];
#pragma unroll
        for (int p = 0; p < 8; p++) { a0[p] = 0ULL; a1[p] = 0ULL; }
#pragma unroll 4
        for (int k2 = 0; k2 < 16; k2++) {
            ulonglong2 wA = *(const ulonglong2*)(wlT + (2 * k2) * 128);
            ulonglong2 wB = *(const ulonglong2*)(wlT + (2 * k2 + 1) * 128);
#pragma unroll
            for (int p = 0; p < 8; p++) {
                ulonglong2 xv = *(const ulonglong2*)&xsp[w][p * 32 + 2 * k2];
                FMA2(a0[p], xv.x, wA.x); FMA2(a1[p], xv.x, wA.y);
                FMA2(a0[p], xv.y, wB.x); FMA2(a1[p], xv.y, wB.y);
            }
        }
#pragma unroll
        for (int p = 0; p < 8; p++) {
            int vid = vids[w][p];
            if (vid != cur) {
                if (cur >= 0) {
                    int slot = head + ns; if (slot >= 12) slot -= 12;
                    *(float4*)&stash[w][slot][lane * 4] = make_float4(m0, m1, m2, m3);
                    if (lane == 0) svid[w][slot] = cur;
                    ns++;
                }
                m0 = NEG; m1 = NEG; m2 = NEG; m3 = NEG;
                cur = vid;
            }
            float y0, y1, y2, y3;
            unpack2(a0[p], y0, y1); unpack2(a1[p], y2, y3);
            m0 = fmaxf(m0, y0); m1 = fmaxf(m1, y1);
            m2 = fmaxf(m2, y2); m3 = fmaxf(m3, y3);
        }
        __syncwarp();
        while (ns >= 4) drain(4);     // leaves ns <= 3; next iter adds <= 8 => ns <= 11 < 12
    }
    if (cur >= 0) {
        int slot = head + ns; if (slot >= 12) slot -= 12;
        *(float4*)&stash[w][slot][lane * 4] = make_float4(m0, m1, m2, m3);
        if (lane == 0) svid[w][slot] = cur;
        ns++;
    }
    __syncwarp();
    while (ns > 0) drain(min(ns, 4));
}

// -------------------- host --------------------
extern "C" void kernel_launch(void* const* d_in, const int* in_sizes, int n_in,
                              void* d_out, int out_size) {
    const float* pts = (const float*)d_in[0];
    const float* w0  = (const float*)d_in[1];
    const float* g0  = (const float*)d_in[2];
    const float* b0  = (const float*)d_in[3];
    const float* w1  = (const float*)d_in[4];
    const float* g1  = (const float*)d_in[5];
    const float* b1  = (const float*)d_in[6];
    float* out = (float*)d_out;

    int n = in_sizes[0] / 5;
    if (n > NMAX) n = NMAX;
    int Vh = out_size / 132;
    int nb = (NCELLS + 1023) / 1024;

    k_zero    <<<(NCELLS + 255) / 256, 256>>>();
    k_points  <<<(n + 255) / 256, 256>>>(pts, n);
    k_scan1   <<<nb, 1024>>>();
    k_scan2   <<<1, 256>>>(nb);
    k_cells   <<<(NCELLS + 255) / 256, 256>>>(out, Vh);
    k_scatfeat<<<1480, 256>>>(pts, n);
    k_bnfin0  <<<1, 32>>>(g0, b0, w0);
    k_l0post  <<<1480, 256>>>(pts, w0);
    k_statsA  <<<512, 256>>>();
    k_statsBC <<<256, 256>>>();
    k_bnfin1  <<<128, 64>>>(w1, g1, b1);
    k_prepw   <<<16, 256>>>(w1);
    k_l1a     <<<2960, 256>>>(out, Vh);
}

// round 16
// speedup vs baseline: 1.5155x; 1.5155x over previous
#include <cuda_runtime.h>

#define NMAX   1000000
#define NCELLS 220000
#define GX 220
#define GY 250

// -------------------- static scratch --------------------
static __device__ int    d_key[NMAX];
static __device__ int    d_rank[NMAX];
static __device__ __align__(8) int2 d_pvinv[NMAX];     // {voxel id, original index}
static __device__ int    d_cnt[NCELLS];
static __device__ int    d_cellvid[NCELLS];
static __device__ int    d_cellstart[NCELLS];
static __device__ float  d_sums[NCELLS * 3];
static __device__ float  d_mean[NCELLS * 3];
static __device__ int    d_voxstart[NCELLS + 1];
static __device__ int    d_voxcnt[NCELLS];
static __device__ int    d_voxcell[NCELLS];
static __device__ __align__(16) float d_x[(size_t)NMAX * 32];
static __device__ __align__(16) float d_xmax[(size_t)NCELLS * 32];
static __device__ __align__(16) float d_xsum[(size_t)NCELLS * 32];
static __device__ __align__(16) float d_w1p[4096];   // sc-scaled top weights (32x128)
static __device__ __align__(16) float d_w1b[4096];   // sc-scaled bottom weights (32x128)
static __device__ double d_S0t[55];   // 10x10 Gram, upper triangle
static __device__ double d_svf[10];
static __device__ double d_SA[1024];
static __device__ double d_SB[1024];
static __device__ double d_SC[1024];
static __device__ double d_svx[32];
static __device__ double d_svm[32];
static __device__ float  d_bn0[64];
static __device__ float  d_bn1[256];
static __device__ unsigned long long d_bsum[256];
static __device__ int    d_meta[2];    // [0]=V, [1]=Nvalid

__device__ __forceinline__ int3 coordsOf(float x, float y, float z) {
    int ix = (int)floorf(__fdiv_rn(x, 0.32f));
    int iy = (int)floorf(__fdiv_rn(__fadd_rn(y, 40.0f), 0.32f));
    int iz = (int)floorf(__fdiv_rn(__fadd_rn(z, 3.0f), 4.0f));
    return make_int3(ix, iy, iz);
}
__device__ __forceinline__ unsigned long long splat2(float v) {
    unsigned long long r;
    asm("mov.b64 %0, {%1, %1};" : "=l"(r) : "r"(__float_as_uint(v)));
    return r;
}
__device__ __forceinline__ unsigned long long pack2(float a, float b) {
    unsigned long long r;
    asm("mov.b64 %0, {%1, %2};" : "=l"(r) : "r"(__float_as_uint(a)), "r"(__float_as_uint(b)));
    return r;
}
__device__ __forceinline__ void unpack2(unsigned long long p, float& a, float& b) {
    unsigned int lo, hi;
    asm("mov.b64 {%0, %1}, %2;" : "=r"(lo), "=r"(hi) : "l"(p));
    a = __uint_as_float(lo); b = __uint_as_float(hi);
}
#define FMA2(acc, a, b) asm("fma.rn.f32x2 %0, %1, %2, %0;" : "+l"(acc) : "l"(a), "l"(b))

// -------------------- K0: zero --------------------
__global__ void k_zero() {
    int i = blockIdx.x * blockDim.x + threadIdx.x;
    if (i < NCELLS) {
        d_cnt[i] = 0;
        d_sums[i * 3 + 0] = 0.f; d_sums[i * 3 + 1] = 0.f; d_sums[i * 3 + 2] = 0.f;
    }
    if (i < 1024) { d_SA[i] = 0.0; d_SB[i] = 0.0; d_SC[i] = 0.0; }
    if (i < 55)   d_S0t[i] = 0.0;
    if (i < 10)   d_svf[i] = 0.0;
    if (i < 32)   { d_svx[i] = 0.0; d_svm[i] = 0.0; }
}

// -------------------- K1: keys + histogram (rank) + xyz sums --------------------
__global__ void k_points(const float* __restrict__ pts, int n) {
    int i = blockIdx.x * blockDim.x + threadIdx.x;
    if (i >= n) return;
    const float* p = pts + (size_t)i * 5;
    float b = p[0], x = p[1], y = p[2], z = p[3];
    int3 c = coordsOf(x, y, z);
    int key = -1;
    if (c.x >= 0 && c.x < GX && c.y >= 0 && c.y < GY && c.z == 0) {
        key = (int)b * 55000 + c.x * 250 + c.y;
        if (key < 0 || key >= NCELLS) key = -1;
    }
    d_key[i] = key;
    if (key >= 0) {
        d_rank[i] = atomicAdd(&d_cnt[key], 1);
        atomicAdd(&d_sums[key * 3 + 0], x);
        atomicAdd(&d_sums[key * 3 + 1], y);
        atomicAdd(&d_sums[key * 3 + 2], z);
    }
}

// -------------------- K2: packed scans (shfl) --------------------
__global__ void k_scan1() {
    __shared__ unsigned long long wsum[32];
    int tid = threadIdx.x;
    int wid = tid >> 5, lane = tid & 31;
    int c = blockIdx.x * 1024 + tid;
    unsigned long long v = 0ULL;
    if (c < NCELLS) {
        int cn = d_cnt[c];
        v = ((unsigned long long)(cn > 0) << 32) | (unsigned int)cn;
    }
    unsigned long long s = v;
#pragma unroll
    for (int o = 1; o < 32; o <<= 1) {
        unsigned long long t = __shfl_up_sync(0xffffffffu, s, o);
        if (lane >= o) s += t;
    }
    if (lane == 31) wsum[wid] = s;
    __syncthreads();
    if (wid == 0) {
        unsigned long long ws = wsum[lane];
        unsigned long long t2 = ws;
#pragma unroll
        for (int o = 1; o < 32; o <<= 1) {
            unsigned long long t = __shfl_up_sync(0xffffffffu, t2, o);
            if (lane >= o) t2 += t;
        }
        wsum[lane] = t2 - ws;   // exclusive warp offsets
    }
    __syncthreads();
    unsigned long long exc = s - v + wsum[wid];
    if (c < NCELLS) {
        d_cellvid[c]   = (int)(exc >> 32);
        d_cellstart[c] = (int)(exc & 0xffffffffULL);
    }
    if (tid == 1023) d_bsum[blockIdx.x] = exc + v;
}

__global__ void k_scan2(int nb) {
    __shared__ unsigned long long s[256];
    int t = threadIdx.x;
    unsigned long long v = (t < nb) ? d_bsum[t] : 0ULL;
    s[t] = v;
    __syncthreads();
    for (int o = 1; o < 256; o <<= 1) {
        unsigned long long u = (t >= o) ? s[t - o] : 0ULL;
        __syncthreads();
        s[t] += u;
        __syncthreads();
    }
    if (t < nb) d_bsum[t] = s[t] - v;
    if (t == 255) {
        d_meta[0] = (int)(s[255] >> 32);
        d_meta[1] = (int)(s[255] & 0xffffffffULL);
    }
}

// -------------------- K3: finalize cells + coords output --------------------
__global__ void k_cells(float* __restrict__ out, int Vh) {
    int c = blockIdx.x * blockDim.x + threadIdx.x;
    if (c >= NCELLS) return;
    unsigned long long off = d_bsum[c >> 10];
    int vid = d_cellvid[c]   + (int)(off >> 32);
    int cst = d_cellstart[c] + (int)(off & 0xffffffffULL);
    d_cellvid[c] = vid;
    d_cellstart[c] = cst;
    int cn = d_cnt[c];
    if (cn > 0) {
        d_voxstart[vid] = cst;
        d_voxcnt[vid]   = cn;
        d_voxcell[vid]  = c;
        float fn = (float)cn;
        d_mean[vid * 3 + 0] = d_sums[c * 3 + 0] / fn;
        d_mean[vid * 3 + 1] = d_sums[c * 3 + 1] / fn;
        d_mean[vid * 3 + 2] = d_sums[c * 3 + 2] / fn;
        if (vid < Vh) {
            int b = c / 55000; int rem = c - b * 55000;
            int cx = rem / 250; int cy = rem - cx * 250;
            float* oc = out + (size_t)Vh * 128 + (size_t)vid * 4;
            oc[0] = (float)b; oc[1] = 0.f; oc[2] = (float)cy; oc[3] = (float)cx;
        }
    }
}

// -------------------- K4: scatter (vid,idx) + 10x10 Gram (fused) ----------------
__global__ void __launch_bounds__(256) k_scatfeat(const float* __restrict__ pts, int n) {
    float G[55], sv[10];
#pragma unroll
    for (int j = 0; j < 55; j++) G[j] = 0.f;
#pragma unroll
    for (int j = 0; j < 10; j++) sv[j] = 0.f;

    const float XO = (float)(0.32 / 2 + 0.0);
    const float YO = (float)(0.32 / 2 - 40.0);
    const float ZO = (float)(4.0 / 2 - 3.0);

    for (int i = blockIdx.x * blockDim.x + threadIdx.x; i < n;
         i += gridDim.x * blockDim.x) {
        int k = d_key[i];
        if (k < 0) continue;
        const float* p = pts + (size_t)i * 5;
        float x = p[1], y = p[2], z = p[3], it = p[4];
        int3 c = coordsOf(x, y, z);
        int v = d_cellvid[k];
        int pos = d_cellstart[k] + d_rank[i];
        d_pvinv[pos] = make_int2(v, i);
        float f[10];
        f[0] = x; f[1] = y; f[2] = z; f[3] = it;
        f[4] = x - d_mean[v * 3 + 0];
        f[5] = y - d_mean[v * 3 + 1];
        f[6] = z - d_mean[v * 3 + 2];
        f[7] = x - ((float)c.x * 0.32f + XO);
        f[8] = y - ((float)c.y * 0.32f + YO);
        f[9] = z - ZO;
        int gi = 0;
#pragma unroll
        for (int a = 0; a < 10; a++) {
            sv[a] += f[a];
#pragma unroll
            for (int bb = a; bb < 10; bb++) {
                G[gi] = fmaf(f[a], f[bb], G[gi]);
                gi++;
            }
        }
    }

    __shared__ float red[8][66];
    int w = threadIdx.x >> 5, lane = threadIdx.x & 31;
#pragma unroll
    for (int j = 0; j < 55; j++) {
        float v = G[j];
#pragma unroll
        for (int o = 16; o > 0; o >>= 1) v += __shfl_xor_sync(0xffffffffu, v, o);
        if (lane == 0) red[w][j] = v;
    }
#pragma unroll
    for (int j = 0; j < 10; j++) {
        float v = sv[j];
#pragma unroll
        for (int o = 16; o > 0; o >>= 1) v += __shfl_xor_sync(0xffffffffu, v, o);
        if (lane == 0) red[w][55 + j] = v;
    }
    __syncthreads();
    int t = threadIdx.x;
    if (t < 65) {
        float a = 0.f;
#pragma unroll
        for (int j = 0; j < 8; j++) a += red[j][t];
        if (t < 55) atomicAdd(&d_S0t[t], (double)a);
        else        atomicAdd(&d_svf[t - 55], (double)a);
    }
}

// -------------------- K5: BN0 params (triangular Gram) --------------------
__device__ __forceinline__ float S0at(int i, int j) {
    if (i > j) { int t = i; i = j; j = t; }
    int idx = i * 10 - (i * (i - 1)) / 2 + (j - i);
    return (float)d_S0t[idx];
}

__global__ void k_bnfin0(const float* __restrict__ g, const float* __restrict__ b,
                         const float* __restrict__ w0) {
    int c = threadIdx.x;
    if (c >= 32) return;
    float n = (float)d_meta[1];
    float sm = 0.f;
#pragma unroll
    for (int k = 0; k < 10; k++) sm = fmaf((float)d_svf[k], w0[k * 32 + c], sm);
    float mu = sm / n;
    float sq = 0.f;
    for (int i = 0; i < 10; i++) {
        float wi = w0[i * 32 + c];
        float row = 0.f;
        for (int j = 0; j < 10; j++)
            row = fmaf(S0at(i, j), w0[j * 32 + c], row);
        sq = fmaf(wi, row, sq);
    }
    float var = sq / n - mu * mu;
    float istd = rsqrtf(var + 1e-3f);
    float sc = g[c] * istd;
    d_bn0[c] = sc;
    d_bn0[32 + c] = b[c] - mu * sc;
}

// -------------------- K6: layer0 via per-voxel affine form + xmax + xsum --------
__global__ void __launch_bounds__(256) k_l0post(const float* __restrict__ pts,
                                                const float* __restrict__ w0) {
    int t = threadIdx.x;
    int w = t >> 5, lane = t & 31;
    float wc[10];
#pragma unroll
    for (int k = 0; k < 10; k++) wc[k] = w0[k * 32 + lane];
    float sc = d_bn0[lane], sh = d_bn0[32 + lane];
    float WX = (wc[0] + wc[4] + wc[7]) * sc;
    float WY = (wc[1] + wc[5] + wc[8]) * sc;
    float WZ = (wc[2] + wc[6] + wc[9]) * sc;
    float WI = wc[3] * sc;
    const float XO = (float)(0.32 / 2 + 0.0);
    const float YO = (float)(0.32 / 2 - 40.0);
    const float ZO = (float)(4.0 / 2 - 3.0);
    int V = d_meta[0];
    for (int v = blockIdx.x * 8 + w; v < V; v += gridDim.x * 8) {
        int st = d_voxstart[v], en = st + d_voxcnt[v];
        int c = d_voxcell[v];
        float mx = d_mean[v * 3 + 0], my = d_mean[v * 3 + 1], mz = d_mean[v * 3 + 2];
        int rem = c % 55000;
        float CCX = (float)(rem / 250) * 0.32f + XO;
        float CCY = (float)(rem % 250) * 0.32f + YO;
        float K = sh - (mx * wc[4] + my * wc[5] + mz * wc[6] +
                        CCX * wc[7] + CCY * wc[8] + ZO * wc[9]) * sc;
        float m = 0.f, s = 0.f;
        for (int p = st; p < en; p++) {
            int ii = d_pvinv[p].y;
            const float* pp = pts + (size_t)ii * 5;
            float pv = (lane < 4) ? pp[1 + lane] : 0.f;
            float px = __shfl_sync(0xffffffffu, pv, 0);
            float py = __shfl_sync(0xffffffffu, pv, 1);
            float pz = __shfl_sync(0xffffffffu, pv, 2);
            float pi = __shfl_sync(0xffffffffu, pv, 3);
            float y = fmaf(px, WX, fmaf(py, WY, fmaf(pz, WZ, fmaf(pi, WI, K))));
            float x = fmaxf(y, 0.f);
            d_x[(size_t)p * 32 + lane] = x;
            m = fmaxf(m, x); s += x;
        }
        d_xmax[(size_t)v * 32 + lane] = m;
        d_xsum[(size_t)v * 32 + lane] = s;
    }
}

// -------------------- K7: SA = Σ x xᵀ (4x4 tiles, low crossbar) -----------------
__global__ void __launch_bounds__(256) k_statsA() {
    __shared__ __align__(16) float xs[1024];
    __shared__ float red[4][64][16];
    int t = threadIdx.x;
    int g = t >> 6, u = t & 63;
    int r4 = ((u >> 3) & 7) << 2, c4 = (u & 7) << 2;
    int N = d_meta[1];
    int N32 = N * 32;
    int nch = (N + 31) >> 5;
    unsigned long long acc[8];
#pragma unroll
    for (int j = 0; j < 8; j++) acc[j] = 0ULL;
    for (int ch = blockIdx.x; ch < nch; ch += gridDim.x) {
        int base = ch * 1024 + t * 4;
        float4 v = make_float4(0.f, 0.f, 0.f, 0.f);
        if (base < N32) v = *(const float4*)(d_x + base);
        *(float4*)&xs[t * 4] = v;
        __syncthreads();
#pragma unroll 4
        for (int pp = 0; pp < 8; pp++) {
            int p = g * 8 + pp;
            float4 xc = *(float4*)&xs[p * 32 + c4];
            unsigned long long c01 = pack2(xc.x, xc.y);
            unsigned long long c23 = pack2(xc.z, xc.w);
#pragma unroll
            for (int j = 0; j < 4; j++) {
                unsigned long long xr2 = splat2(xs[p * 32 + r4 + j]);
                FMA2(acc[2 * j], xr2, c01);
                FMA2(acc[2 * j + 1], xr2, c23);
            }
        }
        __syncthreads();
    }
    float vals[16];
#pragma unroll
    for (int j = 0; j < 8; j++) unpack2(acc[j], vals[2 * j], vals[2 * j + 1]);
#pragma unroll
    for (int k = 0; k < 16; k++) red[g][u][k] = vals[k];
    __syncthreads();
    if (t < 64) {
#pragma unroll
        for (int k = 0; k < 16; k++) {
            float s = red[0][t][k] + red[1][t][k] + red[2][t][k] + red[3][t][k];
            int jr = k >> 2, jc = k & 3;
            atomicAdd(&d_SA[(r4 + jr) * 32 + c4 + jc], (double)s);
        }
    }
}

// -------------------- K8: SB, SC, svx, svm --------------------
__global__ void __launch_bounds__(256) k_statsBC() {
    __shared__ __align__(16) float ms[1024];
    __shared__ __align__(16) float sxs[1024];
    __shared__ float cnf[32];
    int t = threadIdx.x;
    int V = d_meta[0];
    int V32 = V * 32;
    int nch = (V + 31) >> 5;
    int r = t >> 3, c4 = (t & 7) << 2;
    unsigned long long B01 = 0, B23 = 0, C01 = 0, C23 = 0;
    float vx[4] = {0, 0, 0, 0}, vm[4] = {0, 0, 0, 0};
    for (int ch = blockIdx.x; ch < nch; ch += gridDim.x) {
        int base = ch * 1024 + t * 4;
        float4 mv = make_float4(0, 0, 0, 0), sv = make_float4(0, 0, 0, 0);
        if (base < V32) {
            mv = *(const float4*)(d_xmax + base);
            sv = *(const float4*)(d_xsum + base);
        }
        *(float4*)&ms[t * 4] = mv;
        *(float4*)&sxs[t * 4] = sv;
        if (t < 32) {
            int vv = ch * 32 + t;
            cnf[t] = (vv < V) ? (float)d_voxcnt[vv] : 0.f;
        }
        __syncthreads();
#pragma unroll 4
        for (int p = 0; p < 32; p++) {
            float cn = cnf[p];
            unsigned long long sxr2 = splat2(sxs[p * 32 + r]);
            unsigned long long cmr2 = splat2(cn * ms[p * 32 + r]);
            float4 m4 = *(float4*)&ms[p * 32 + c4];
            unsigned long long m01 = pack2(m4.x, m4.y);
            unsigned long long m23 = pack2(m4.z, m4.w);
            FMA2(B01, sxr2, m01); FMA2(B23, sxr2, m23);
            FMA2(C01, cmr2, m01); FMA2(C23, cmr2, m23);
            if (t < 8) {
                float4 sx4 = *(float4*)&sxs[p * 32 + c4];
                vx[0] += sx4.x; vx[1] += sx4.y; vx[2] += sx4.z; vx[3] += sx4.w;
                vm[0] = fmaf(cn, m4.x, vm[0]); vm[1] = fmaf(cn, m4.y, vm[1]);
                vm[2] = fmaf(cn, m4.z, vm[2]); vm[3] = fmaf(cn, m4.w, vm[3]);
            }
        }
        __syncthreads();
    }
    float b0, b1, b2, b3, c0, c1, c2, c3;
    unpack2(B01, b0, b1); unpack2(B23, b2, b3);
    unpack2(C01, c0, c1); unpack2(C23, c2, c3);
    atomicAdd(&d_SB[r * 32 + c4 + 0], (double)b0);
    atomicAdd(&d_SB[r * 32 + c4 + 1], (double)b1);
    atomicAdd(&d_SB[r * 32 + c4 + 2], (double)b2);
    atomicAdd(&d_SB[r * 32 + c4 + 3], (double)b3);
    atomicAdd(&d_SC[r * 32 + c4 + 0], (double)c0);
    atomicAdd(&d_SC[r * 32 + c4 + 1], (double)c1);
    atomicAdd(&d_SC[r * 32 + c4 + 2], (double)c2);
    atomicAdd(&d_SC[r * 32 + c4 + 3], (double)c3);
    if (t < 8) {
#pragma unroll
        for (int j = 0; j < 4; j++) {
            atomicAdd(&d_svx[c4 + j], (double)vx[j]);
            atomicAdd(&d_svm[c4 + j], (double)vm[j]);
        }
    }
}

// -------------------- K9: BN1 params --------------------
__device__ __forceinline__ float S64(int i, int j) {
    if (i < 32) {
        if (j < 32) return (float)d_SA[i * 32 + j];
        return (float)d_SB[i * 32 + (j - 32)];
    } else {
        if (j < 32) return (float)d_SB[j * 32 + (i - 32)];
        return (float)d_SC[(i - 32) * 32 + (j - 32)];
    }
}

__global__ void k_bnfin1(const float* __restrict__ w1, const float* __restrict__ g,
                         const float* __restrict__ b) {
    __shared__ float wc[64];
    __shared__ float red[64];
    __shared__ float red2[64];
    int c = blockIdx.x;
    int i = threadIdx.x;
    float wi = w1[i * 128 + c];
    wc[i] = wi;
    float sv = (i < 32) ? (float)d_svx[i] : (float)d_svm[i - 32];
    __syncthreads();
    float row = 0.f;
    for (int j = 0; j < 64; j++) row = fmaf(S64(i, j), wc[j], row);
    red[i] = wi * row;
    red2[i] = sv * wi;
    __syncthreads();
    for (int o = 32; o > 0; o >>= 1) {
        if (i < o) { red[i] += red[i + o]; red2[i] += red2[i + o]; }
        __syncthreads();
    }
    if (i == 0) {
        float n = (float)d_meta[1];
        float mu = red2[0] / n;
        float var = red[0] / n - mu * mu;
        float istd = rsqrtf(var + 1e-3f);
        float sc = g[c] * istd;
        d_bn1[c] = sc;
        d_bn1[128 + c] = b[c] - mu * sc;
    }
}

// -------------------- K10: pre-scale weights + voxstart sentinel ----------------
__global__ void k_prepw(const float* __restrict__ w1) {
    int i = blockIdx.x * blockDim.x + threadIdx.x;
    if (i == 0) d_voxstart[d_meta[0]] = d_meta[1];
    if (i < 4096) {
        float sc = d_bn1[i & 127];
        d_w1p[i] = w1[i] * sc;
        d_w1b[i] = w1[4096 + i] * sc;
    }
}

// -------------------- K11: fused point GEMM + seg max + voxel GEMM + out --------
__global__ void __launch_bounds__(256) k_l1a(float* __restrict__ out, int Vh) {
    __shared__ __align__(16) float wst[4096];                 // Wtop'
    __shared__ __align__(16) float wsb[4096];                 // Wbot'
    __shared__ __align__(16) unsigned long long xsp[8][256];
    __shared__ __align__(16) float stash[8][16][128];
    __shared__ int svid[8][16];
    __shared__ int vids[8][9];
    for (int j = threadIdx.x; j < 1024; j += 256) {
        ((float4*)wst)[j] = ((const float4*)d_w1p)[j];
        ((float4*)wsb)[j] = ((const float4*)d_w1b)[j];
    }
    __syncthreads();
    int w = threadIdx.x >> 5, lane = threadIdx.x & 31;
    int N = d_meta[1], V = d_meta[0];
    int nw = gridDim.x * 8;
    int gw = blockIdx.x * 8 + w;
    int CH = (N + nw - 1) / nw;
    int lo = gw * CH;
    if (lo >= N) return;
    int hi = min(N, lo + CH);
    int a = 0, b = V;
    while (a < b) { int m = (a + b) >> 1; if (d_voxstart[m] < lo) a = m + 1; else b = m; }
    int vb = a;
    int a2 = vb, b2 = V;
    while (a2 < b2) { int m = (a2 + b2) >> 1; if (d_voxstart[m] < hi) a2 = m + 1; else b2 = m; }
    int pst = d_voxstart[vb];
    int pen = d_voxstart[a2];
    if (pst >= pen) return;

    const float NEG = __int_as_float(0xff800000);
    const float* wlT = wst + lane * 4;
    const float* wlB = wsb + lane * 4;
    float4 sh4 = *(const float4*)(d_bn1 + 128 + lane * 4);
    float m0 = NEG, m1 = NEG, m2 = NEG, m3 = NEG;
    int cur = -1, ns = 0, head = 0;

    auto drain = [&](int count) {
        for (int j = lane; j < 64; j += 32) {
            int p = j >> 3, q = j & 7;
            float4 v = make_float4(0.f, 0.f, 0.f, 0.f);
            if (p < count) {
                int gv = svid[w][(head + p) & 15];
                v = *(const float4*)(d_xmax + (size_t)gv * 32 + q * 4);
            }
            unsigned long long* d = &xsp[w][p * 32 + q * 4];
            d[0] = splat2(v.x); d[1] = splat2(v.y); d[2] = splat2(v.z); d[3] = splat2(v.w);
        }
        __syncwarp();
        unsigned long long b0[8], b1[8];
#pragma unroll
        for (int p = 0; p < 8; p++) { b0[p] = 0ULL; b1[p] = 0ULL; }
#pragma unroll 4
        for (int k2 = 0; k2 < 16; k2++) {
            ulonglong2 wA = *(const ulonglong2*)(wlB + (2 * k2) * 128);
            ulonglong2 wB = *(const ulonglong2*)(wlB + (2 * k2 + 1) * 128);
#pragma unroll
            for (int p = 0; p < 8; p++) {
                ulonglong2 xv = *(const ulonglong2*)&xsp[w][p * 32 + 2 * k2];
                FMA2(b0[p], xv.x, wA.x); FMA2(b1[p], xv.x, wA.y);
                FMA2(b0[p], xv.y, wB.x); FMA2(b1[p], xv.y, wB.y);
            }
        }
        __syncwarp();
#pragma unroll
        for (int p = 0; p < 8; p++) {
            if (p >= count) break;
            int slot = (head + p) & 15;
            int vv = svid[w][slot];
            float y0, y1, y2, y3;
            unpack2(b0[p], y0, y1); unpack2(b1[p], y2, y3);
            float4 mm = *(float4*)&stash[w][slot][lane * 4];
            if (vv < Vh) {
                float o0 = fmaxf(mm.x + y0 + sh4.x, 0.f);
                float o1 = fmaxf(mm.y + y1 + sh4.y, 0.f);
                float o2 = fmaxf(mm.z + y2 + sh4.z, 0.f);
                float o3 = fmaxf(mm.w + y3 + sh4.w, 0.f);
                *(float4*)(out + (size_t)vv * 128 + lane * 4) = make_float4(o0, o1, o2, o3);
            }
        }
        head = (head + count) & 15;
        ns -= count;
    };

    for (int base = pst; base < pen; base += 8) {
        for (int j = lane; j < 64; j += 32) {
            int p = j >> 3, q = j & 7;
            int gp = base + p;
            float4 v = make_float4(0.f, 0.f, 0.f, 0.f);
            if (gp < pen) v = *(const float4*)(d_x + (size_t)gp * 32 + q * 4);
            unsigned long long* d = &xsp[w][p * 32 + q * 4];
            d[0] = splat2(v.x); d[1] = splat2(v.y); d[2] = splat2(v.z); d[3] = splat2(v.w);
        }
        if (lane < 9) vids[w][lane] = (base + lane < pen) ? d_pvinv[base + lane].x : -1;
        __syncwarp();
        unsigned long long a0[8], a1[8];
#pragma unroll
        for (int p = 0; p < 8; p++) { a0[p] = 0ULL; a1[p] = 0ULL; }
#pragma unroll 4
        for (int k2 = 0; k2 < 16; k2++) {
            ulonglong2 wA = *(const ulonglong2*)(wlT + (2 * k2) * 128);
            ulonglong2 wB = *(const ulonglong2*)(wlT + (2 * k2 + 1) * 128);
#pragma unroll
            for (int p = 0; p < 8; p++) {
                ulonglong2 xv = *(const ulonglong2*)&xsp[w][p * 32 + 2 * k2];
                FMA2(a0[p], xv.x, wA.x); FMA2(a1[p], xv.x, wA.y);
                FMA2(a0[p], xv.y, wB.x); FMA2(a1[p], xv.y, wB.y);
            }
        }
#pragma unroll
        for (int p = 0; p < 8; p++) {
            int vid = vids[w][p];
            if (vid != cur) {
                if (cur >= 0) {
                    int slot = (head + ns) & 15;
                    *(float4*)&stash[w][slot][lane * 4] = make_float4(m0, m1, m2, m3);
                    if (lane == 0) svid[w][slot] = cur;
                    ns++;
                }
                m0 = NEG; m1 = NEG; m2 = NEG; m3 = NEG;
                cur = vid;
            }
            float y0, y1, y2, y3;
            unpack2(a0[p], y0, y1); unpack2(a1[p], y2, y3);
            m0 = fmaxf(m0, y0); m1 = fmaxf(m1, y1);
            m2 = fmaxf(m2, y2); m3 = fmaxf(m3, y3);
        }
        __syncwarp();
        if (ns >= 8) drain(8);
    }
    if (cur >= 0) {
        int slot = (head + ns) & 15;
        *(float4*)&stash[w][slot][lane * 4] = make_float4(m0, m1, m2, m3);
        if (lane == 0) svid[w][slot] = cur;
        ns++;
    }
    __syncwarp();
    while (ns > 0) drain(min(ns, 8));
}

// -------------------- host --------------------
extern "C" void kernel_launch(void* const* d_in, const int* in_sizes, int n_in,
                              void* d_out, int out_size) {
    const float* pts = (const float*)d_in[0];
    const float* w0  = (const float*)d_in[1];
    const float* g0  = (const float*)d_in[2];
    const float* b0  = (const float*)d_in[3];
    const float* w1  = (const float*)d_in[4];
    const float* g1  = (const float*)d_in[5];
    const float* b1  = (const float*)d_in[6];
    float* out = (float*)d_out;

    int n = in_sizes[0] / 5;
    if (n > NMAX) n = NMAX;
    int Vh = out_size / 132;
    int nb = (NCELLS + 1023) / 1024;

    k_zero    <<<(NCELLS + 255) / 256, 256>>>();
    k_points  <<<(n + 255) / 256, 256>>>(pts, n);
    k_scan1   <<<nb, 1024>>>();
    k_scan2   <<<1, 256>>>(nb);
    k_cells   <<<(NCELLS + 255) / 256, 256>>>(out, Vh);
    k_scatfeat<<<1480, 256>>>(pts, n);
    k_bnfin0  <<<1, 32>>>(g0, b0, w0);
    k_l0post  <<<1480, 256>>>(pts, w0);
    k_statsA  <<<512, 256>>>();
    k_statsBC <<<256, 256>>>();
    k_bnfin1  <<<128, 64>>>(w1, g1, b1);
    k_prepw   <<<16, 256>>>(w1);
    k_l1a     <<<1480, 256>>>(out, Vh);
}